// round 13
// baseline (speedup 1.0000x reference)
#include <cuda_runtime.h>
#include <cuda_fp16.h>
#include <cstdint>

#define T_LEN 1024
#define NTH   512
#define HSTR  72         // halves per row (144 B = 9*16B): 16B-aligned, conflict-free

static __device__ __forceinline__ float tanhapx(float x) {
    float y;
    asm("tanh.approx.f32 %0, %1;" : "=f"(y) : "f"(x));
    return y;
}
static __device__ __forceinline__ float fsig(float x) {
    return fmaf(0.5f, tanhapx(0.5f * x), 0.5f);
}
static __device__ __forceinline__ uint32_t pack2(float a, float b) {
    __half2 t = __halves2half2(__float2half_rn(a), __float2half_rn(b));
    return *(uint32_t*)&t;
}
// 64-col permutation: h col c -> fragment-vectorized position (validated R10/R11)
static __device__ __forceinline__ int perm64(int c) {
    return (((c & 7) >> 1) << 4) + ((c >> 4) << 2) + (((c >> 3) & 1) << 1) + (c & 1);
}
static __device__ __forceinline__ void mma16816(float* d, const uint32_t* a, const uint32_t* b) {
    asm volatile(
        "mma.sync.aligned.m16n8k16.row.col.f32.f16.f16.f32 "
        "{%0,%1,%2,%3}, {%4,%5,%6,%7}, {%8,%9}, {%0,%1,%2,%3};"
        : "+f"(d[0]), "+f"(d[1]), "+f"(d[2]), "+f"(d[3])
        : "r"(a[0]), "r"(a[1]), "r"(a[2]), "r"(a[3]), "r"(b[0]), "r"(b[1]));
}

__global__ void out_init(float* out, const float* fc_b, int n) {
    int i = blockIdx.x * blockDim.x + threadIdx.x;
    if (i < n) out[i] = fc_b[0];
}

__global__ __launch_bounds__(NTH, 1)
void bilstm_mma(const float* __restrict__ x,
                const float* __restrict__ Wih_f, const float* __restrict__ Whh_f,
                const float* __restrict__ bih_f, const float* __restrict__ bhh_f,
                const float* __restrict__ Wih_b, const float* __restrict__ Whh_b,
                const float* __restrict__ bih_b, const float* __restrict__ bhh_b,
                const float* __restrict__ fc_w, float* __restrict__ out)
{
    __shared__ __align__(16) __half hs[2][16][HSTR];   // h (fp16) in frag-permuted order
    __shared__ float psum[2][16][16];

    const int tid = threadIdx.x, wid = tid >> 5, lane = tid & 31;
    const int q = lane & 3, r = lane >> 2;
    const int dir = blockIdx.x & 1;
    const int b0 = (blockIdx.x >> 1) * 16;

    const float* Whh = dir ? Whh_b : Whh_f;
    const float* Wih = dir ? Wih_b : Wih_f;
    const float* bih = dir ? bih_b : bih_f;
    const float* bhh = dir ? bhh_b : bhh_f;

    for (int i = tid; i < 2 * 16 * HSTR; i += NTH) (&hs[0][0][0])[i] = __float2half(0.f);

    // ---- B fragments (Whh^T), fp16 W: warp owns units 4*wid..4*wid+3 ----
    // nt=0: i/g rows interleaved; nt=1: f/o rows interleaved
    uint32_t bf[4][2][2];
    {
        const int qp = r >> 1, odd = r & 1;
        const int unit = 4 * wid + qp;
        #pragma unroll
        for (int nt = 0; nt < 2; ++nt) {
            const int row = (nt == 0) ? (odd ? 128 + unit : unit)
                                      : (odd ? 192 + unit : 64 + unit);
            const float* wr = Whh + row * 64;
            #pragma unroll
            for (int ks = 0; ks < 4; ++ks) {
                const int wcol = ks * 16 + q * 2;
                bf[ks][nt][0] = pack2(__ldg(wr + wcol),     __ldg(wr + wcol + 1));
                bf[ks][nt][1] = pack2(__ldg(wr + wcol + 8), __ldg(wr + wcol + 9));
            }
        }
    }

    // gate-owner: unit uu = 4*wid + q; streams r, r+8
    const int uu = 4 * wid + q;
    const float wi_i = Wih[uu], wi_f = Wih[64 + uu], wi_g = Wih[128 + uu], wi_o = Wih[192 + uu];
    const float bi = bih[uu] + bhh[uu],             bfc = bih[64 + uu] + bhh[64 + uu];
    const float bg = bih[128 + uu] + bhh[128 + uu], bo = bih[192 + uu] + bhh[192 + uu];
    const float fcw = fc_w[dir * 64 + uu];
    const int pc = perm64(uu);

    float cc[2] = {0.f, 0.f};
    __syncthreads();

    for (int t = 0; t < T_LEN; ++t) {
        // flush previous step's fc partials
        if (t > 0 && wid == 0 && lane < 16) {
            const float* ps = &psum[(t - 1) & 1][lane][0];
            float s = 0.f;
            #pragma unroll
            for (int j = 0; j < 16; ++j) s += ps[j];
            atomicAdd(out + (size_t)(b0 + lane) * T_LEN + (t - 1), s);
        }

        const int xt = dir ? (T_LEN - 1 - t) : t;
        const float xv0 = __ldg(x + (size_t)(b0 + r) * T_LEN + xt);
        const float xv1 = __ldg(x + (size_t)(b0 + r + 8) * T_LEN + xt);

        // ---- A fragments: 4x LDS.128 from permuted buffer ----
        const __half* hb = &hs[(t & 1) ^ 1][0][0];
        uint32_t af[4][4];
        {
            const uint4* p0 = (const uint4*)(hb + r * HSTR + q * 16);
            const uint4* p1 = (const uint4*)(hb + (r + 8) * HSTR + q * 16);
            #pragma unroll
            for (int m = 0; m < 2; ++m) {
                const uint4 v = p0[m];
                af[2*m][0] = v.x; af[2*m][2] = v.y; af[2*m+1][0] = v.z; af[2*m+1][2] = v.w;
                const uint4 u = p1[m];
                af[2*m][1] = u.x; af[2*m][3] = u.y; af[2*m+1][1] = u.z; af[2*m+1][3] = u.w;
            }
        }

        // ---- 8 HMMA ----
        float d[2][4] = {{0.f,0.f,0.f,0.f},{0.f,0.f,0.f,0.f}};
        #pragma unroll
        for (int ks = 0; ks < 4; ++ks) {
            mma16816(d[0], af[ks], bf[ks][0]);
            mma16816(d[1], af[ks], bf[ks][1]);
        }

        // ---- gates (thread-local) ----
        __half* hw = &hs[t & 1][0][0];
        float hval[2];
        #pragma unroll
        for (int cidx = 0; cidx < 2; ++cidx) {
            const int co = cidx * 2;
            const float xv = cidx ? xv1 : xv0;
            const float zi = d[0][co]     + fmaf(xv, wi_i, bi);
            const float zg = d[0][co + 1] + fmaf(xv, wi_g, bg);
            const float zf = d[1][co]     + fmaf(xv, wi_f, bfc);
            const float zo = d[1][co + 1] + fmaf(xv, wi_o, bo);
            cc[cidx] = fmaf(fsig(zf), cc[cidx], fsig(zi) * tanhapx(zg));
            hval[cidx] = fsig(zo) * tanhapx(cc[cidx]);
            hw[(cidx ? (r + 8) : r) * HSTR + pc] = __float2half_rn(hval[cidx]);
        }

        // ---- fc partials: reduce over the 4 units (q) of this warp ----
        float p0 = fcw * hval[0], p1 = fcw * hval[1];
        p0 += __shfl_xor_sync(0xffffffffu, p0, 1);
        p0 += __shfl_xor_sync(0xffffffffu, p0, 2);
        p1 += __shfl_xor_sync(0xffffffffu, p1, 1);
        p1 += __shfl_xor_sync(0xffffffffu, p1, 2);
        if (q == 0) {
            psum[t & 1][r][wid] = p0;
            psum[t & 1][r + 8][wid] = p1;
        }
        __syncthreads();
    }

    // final flush
    if (wid == 0 && lane < 16) {
        const float* ps = &psum[(T_LEN - 1) & 1][lane][0];
        float s = 0.f;
        #pragma unroll
        for (int j = 0; j < 16; ++j) s += ps[j];
        atomicAdd(out + (size_t)(b0 + lane) * T_LEN + (T_LEN - 1), s);
    }
}

extern "C" void kernel_launch(void* const* d_in, const int* in_sizes, int n_in,
                              void* d_out, int out_size) {
    const float* x     = (const float*)d_in[0];
    const float* Wih_f = (const float*)d_in[1];
    const float* Whh_f = (const float*)d_in[2];
    const float* bih_f = (const float*)d_in[3];
    const float* bhh_f = (const float*)d_in[4];
    const float* Wih_b = (const float*)d_in[5];
    const float* Whh_b = (const float*)d_in[6];
    const float* bih_b = (const float*)d_in[7];
    const float* bhh_b = (const float*)d_in[8];
    const float* fc_w  = (const float*)d_in[9];
    const float* fc_b  = (const float*)d_in[10];
    float* out = (float*)d_out;

    out_init<<<(out_size + 255) / 256, 256>>>(out, fc_b, out_size);

    const int B = in_sizes[0] / T_LEN;   // 1024
    const int grid = (B / 16) * 2;       // 128 CTAs: (batch-group, direction)
    bilstm_mma<<<grid, NTH>>>(x, Wih_f, Whh_f, bih_f, bhh_f,
                              Wih_b, Whh_b, bih_b, bhh_b, fc_w, out);
    (void)n_in;
}

// round 14
// speedup vs baseline: 1.0650x; 1.0650x over previous
#include <cuda_runtime.h>
#include <cuda_fp16.h>
#include <cstdint>

#define T_LEN 1024
#define NTH   256
#define HSTR  72         // halves per row (144 B = 9*16B): 16B-aligned, conflict-free

static __device__ __forceinline__ uint32_t packh2(float lo, float hi) {
    uint32_t r;
    asm("cvt.rn.f16x2.f32 %0, %1, %2;" : "=r"(r) : "f"(hi), "f"(lo));
    return r;
}
static __device__ __forceinline__ uint32_t tanh2(uint32_t x) {
    uint32_t y;
    asm("tanh.approx.f16x2 %0, %1;" : "=r"(y) : "r"(x));
    return y;
}
static __device__ __forceinline__ uint32_t sig2_from_tanh(uint32_t th) {
    // sigmoid(z) = 0.5*tanh(z/2) + 0.5  (input already tanh(z/2))
    const __half2 h05 = __floats2half2_rn(0.5f, 0.5f);
    __half2 t = *(__half2*)&th;
    __half2 s = __hfma2(t, h05, h05);
    return *(uint32_t*)&s;
}
static __device__ __forceinline__ uint32_t hmul2u(uint32_t a, uint32_t b) {
    __half2 r = __hmul2(*(__half2*)&a, *(__half2*)&b);
    return *(uint32_t*)&r;
}
static __device__ __forceinline__ uint32_t pack2w(float a, float b) {
    __half2 t = __halves2half2(__float2half_rn(a), __float2half_rn(b));
    return *(uint32_t*)&t;
}
// 64-col permutation: h col c -> fragment-vectorized position (validated R10/R11)
static __device__ __forceinline__ int perm64(int c) {
    return (((c & 7) >> 1) << 4) + ((c >> 4) << 2) + (((c >> 3) & 1) << 1) + (c & 1);
}
static __device__ __forceinline__ void mma16816(float* d, const uint32_t* a, const uint32_t* b) {
    asm volatile(
        "mma.sync.aligned.m16n8k16.row.col.f32.f16.f16.f32 "
        "{%0,%1,%2,%3}, {%4,%5,%6,%7}, {%8,%9}, {%0,%1,%2,%3};"
        : "+f"(d[0]), "+f"(d[1]), "+f"(d[2]), "+f"(d[3])
        : "r"(a[0]), "r"(a[1]), "r"(a[2]), "r"(a[3]), "r"(b[0]), "r"(b[1]));
}

__global__ void out_init(float* out, const float* fc_b, int n) {
    int i = blockIdx.x * blockDim.x + threadIdx.x;
    if (i < n) out[i] = fc_b[0];
}

__global__ __launch_bounds__(NTH, 1)
void bilstm_mma(const float* __restrict__ x,
                const float* __restrict__ Wih_f, const float* __restrict__ Whh_f,
                const float* __restrict__ bih_f, const float* __restrict__ bhh_f,
                const float* __restrict__ Wih_b, const float* __restrict__ Whh_b,
                const float* __restrict__ bih_b, const float* __restrict__ bhh_b,
                const float* __restrict__ fc_w, float* __restrict__ out)
{
    __shared__ __align__(16) __half hs[2][16][HSTR];   // h (fp16) in frag-permuted order
    __shared__ float psum[2][16][8];

    const int tid = threadIdx.x, wid = tid >> 5, lane = tid & 31;
    const int q = lane & 3, r = lane >> 2;
    const int dir = blockIdx.x & 1;
    const int b0 = (blockIdx.x >> 1) * 16;

    const float* Whh = dir ? Whh_b : Whh_f;
    const float* Wih = dir ? Wih_b : Wih_f;
    const float* bih = dir ? bih_b : bih_f;
    const float* bhh = dir ? bhh_b : bhh_f;

    for (int i = tid; i < 2 * 16 * HSTR; i += NTH) (&hs[0][0][0])[i] = __float2half(0.f);

    // ---- B fragments (Whh^T), fp16 W: bf[ks 0..3][nt 0..3][2] ----
    uint32_t bf[4][4][2];
    {
        const int qp = r >> 1, odd = r & 1;
        #pragma unroll
        for (int nt = 0; nt < 4; ++nt) {
            const int unit = 8 * wid + (nt >= 2 ? 4 : 0) + qp;
            const int row = ((nt & 1) ? (odd ? 192 : 64) : (odd ? 128 : 0)) + unit;
            const float* wr = Whh + row * 64;
            #pragma unroll
            for (int ks = 0; ks < 4; ++ks) {
                const int wcol = ks * 16 + q * 2;
                bf[ks][nt][0] = pack2w(__ldg(wr + wcol),     __ldg(wr + wcol + 1));
                bf[ks][nt][1] = pack2w(__ldg(wr + wcol + 8), __ldg(wr + wcol + 9));
            }
        }
    }

    // gate-owner: units u1 = 8*wid+q, u2 = u1+4; streams r, r+8
    // sigmoid gates (i,f,o): pre-scaled by 0.5 for tanh-based sigmoid
    const int u1 = 8 * wid + q, u2 = u1 + 4;
    const float wiH_i1 = 0.5f * Wih[u1], wiH_f1 = 0.5f * Wih[64 + u1],
                wi_g1  = Wih[128 + u1],  wiH_o1 = 0.5f * Wih[192 + u1];
    const float wiH_i2 = 0.5f * Wih[u2], wiH_f2 = 0.5f * Wih[64 + u2],
                wi_g2  = Wih[128 + u2],  wiH_o2 = 0.5f * Wih[192 + u2];
    const float biH1 = 0.5f * (bih[u1] + bhh[u1]),        bfH1 = 0.5f * (bih[64 + u1] + bhh[64 + u1]);
    const float bg1  = bih[128 + u1] + bhh[128 + u1];
    const float boH1 = 0.5f * (bih[192 + u1] + bhh[192 + u1]);
    const float biH2 = 0.5f * (bih[u2] + bhh[u2]),        bfH2 = 0.5f * (bih[64 + u2] + bhh[64 + u2]);
    const float bg2  = bih[128 + u2] + bhh[128 + u2];
    const float boH2 = 0.5f * (bih[192 + u2] + bhh[192 + u2]);
    const float fcw1 = fc_w[dir * 64 + u1], fcw2 = fc_w[dir * 64 + u2];
    const int pc1 = perm64(u1), pc2 = perm64(u2);

    float cc[4] = {0.f, 0.f, 0.f, 0.f};
    __syncthreads();

    // x prefetch for t = 0
    const float* xr0 = x + (size_t)(b0 + r) * T_LEN;
    const float* xr1 = x + (size_t)(b0 + r + 8) * T_LEN;
    float xv0 = __ldg(xr0 + (dir ? T_LEN - 1 : 0));
    float xv1 = __ldg(xr1 + (dir ? T_LEN - 1 : 0));

    for (int t = 0; t < T_LEN; ++t) {
        // prefetch x(t+1) — hides L2 latency under this step's compute
        float pxv0 = 0.f, pxv1 = 0.f;
        if (t + 1 < T_LEN) {
            const int nxt = dir ? (T_LEN - 2 - t) : (t + 1);
            pxv0 = __ldg(xr0 + nxt);
            pxv1 = __ldg(xr1 + nxt);
        }

        // flush previous step's fc partials
        if (t > 0 && wid == 0 && lane < 16) {
            const float* ps = &psum[(t - 1) & 1][lane][0];
            float s = 0.f;
            #pragma unroll
            for (int j = 0; j < 8; ++j) s += ps[j];
            atomicAdd(out + (size_t)(b0 + lane) * T_LEN + (t - 1), s);
        }

        // ---- A fragments: 4x LDS.128 from permuted buffer ----
        const __half* hb = &hs[(t & 1) ^ 1][0][0];
        uint32_t af[4][4];
        {
            const uint4* p0 = (const uint4*)(hb + r * HSTR + q * 16);
            const uint4* p1 = (const uint4*)(hb + (r + 8) * HSTR + q * 16);
            #pragma unroll
            for (int m = 0; m < 2; ++m) {
                const uint4 v = p0[m];
                af[2*m][0] = v.x; af[2*m][2] = v.y; af[2*m+1][0] = v.z; af[2*m+1][2] = v.w;
                const uint4 u = p1[m];
                af[2*m][1] = u.x; af[2*m][3] = u.y; af[2*m+1][1] = u.z; af[2*m+1][3] = u.w;
            }
        }

        __half* hw = &hs[t & 1][0][0];
        float hval[4];
        float d[4][4] = {{0.f,0.f,0.f,0.f},{0.f,0.f,0.f,0.f},{0.f,0.f,0.f,0.f},{0.f,0.f,0.f,0.f}};

        // ---- u1: 8 HMMA then f16x2 gates (MUFU overlaps u2's HMMAs) ----
        #pragma unroll
        for (int ks = 0; ks < 4; ++ks) {
            mma16816(d[0], af[ks], bf[ks][0]);
            mma16816(d[1], af[ks], bf[ks][1]);
        }
        {
            const float zi0 = fmaf(0.5f, d[0][0], fmaf(xv0, wiH_i1, biH1));
            const float zi1 = fmaf(0.5f, d[0][2], fmaf(xv1, wiH_i1, biH1));
            const float zg0 = d[0][1] + fmaf(xv0, wi_g1, bg1);
            const float zg1 = d[0][3] + fmaf(xv1, wi_g1, bg1);
            const float zf0 = fmaf(0.5f, d[1][0], fmaf(xv0, wiH_f1, bfH1));
            const float zf1 = fmaf(0.5f, d[1][2], fmaf(xv1, wiH_f1, bfH1));
            const float zo0 = fmaf(0.5f, d[1][1], fmaf(xv0, wiH_o1, boH1));
            const float zo1 = fmaf(0.5f, d[1][3], fmaf(xv1, wiH_o1, boH1));
            const uint32_t i2 = sig2_from_tanh(tanh2(packh2(zi0, zi1)));
            const uint32_t g2 = tanh2(packh2(zg0, zg1));
            const uint32_t f2 = sig2_from_tanh(tanh2(packh2(zf0, zf1)));
            const uint32_t o2 = sig2_from_tanh(tanh2(packh2(zo0, zo1)));
            const uint32_t ig2 = hmul2u(i2, g2);
            const __half2 igh = *(__half2*)&ig2, fh = *(__half2*)&f2;
            cc[0] = fmaf(__low2float(fh),  cc[0], __low2float(igh));
            cc[1] = fmaf(__high2float(fh), cc[1], __high2float(igh));
            const uint32_t c2 = tanh2(packh2(cc[0], cc[1]));
            const uint32_t h2 = hmul2u(o2, c2);
            const __half2 hh = *(__half2*)&h2;
            hw[r * HSTR + pc1]       = __low2half(hh);
            hw[(r + 8) * HSTR + pc1] = __high2half(hh);
            hval[0] = __low2float(hh);
            hval[1] = __high2float(hh);
        }

        // ---- u2: 8 HMMA then gates ----
        #pragma unroll
        for (int ks = 0; ks < 4; ++ks) {
            mma16816(d[2], af[ks], bf[ks][2]);
            mma16816(d[3], af[ks], bf[ks][3]);
        }
        {
            const float zi0 = fmaf(0.5f, d[2][0], fmaf(xv0, wiH_i2, biH2));
            const float zi1 = fmaf(0.5f, d[2][2], fmaf(xv1, wiH_i2, biH2));
            const float zg0 = d[2][1] + fmaf(xv0, wi_g2, bg2);
            const float zg1 = d[2][3] + fmaf(xv1, wi_g2, bg2);
            const float zf0 = fmaf(0.5f, d[3][0], fmaf(xv0, wiH_f2, bfH2));
            const float zf1 = fmaf(0.5f, d[3][2], fmaf(xv1, wiH_f2, bfH2));
            const float zo0 = fmaf(0.5f, d[3][1], fmaf(xv0, wiH_o2, boH2));
            const float zo1 = fmaf(0.5f, d[3][3], fmaf(xv1, wiH_o2, boH2));
            const uint32_t i2 = sig2_from_tanh(tanh2(packh2(zi0, zi1)));
            const uint32_t g2 = tanh2(packh2(zg0, zg1));
            const uint32_t f2 = sig2_from_tanh(tanh2(packh2(zf0, zf1)));
            const uint32_t o2 = sig2_from_tanh(tanh2(packh2(zo0, zo1)));
            const uint32_t ig2 = hmul2u(i2, g2);
            const __half2 igh = *(__half2*)&ig2, fh = *(__half2*)&f2;
            cc[2] = fmaf(__low2float(fh),  cc[2], __low2float(igh));
            cc[3] = fmaf(__high2float(fh), cc[3], __high2float(igh));
            const uint32_t c2 = tanh2(packh2(cc[2], cc[3]));
            const uint32_t h2 = hmul2u(o2, c2);
            const __half2 hh = *(__half2*)&h2;
            hw[r * HSTR + pc2]       = __low2half(hh);
            hw[(r + 8) * HSTR + pc2] = __high2half(hh);
            hval[2] = __low2float(hh);
            hval[3] = __high2float(hh);
        }

        // ---- fc partials ----
        float pr  = fcw1 * hval[0] + fcw2 * hval[2];
        float pr8 = fcw1 * hval[1] + fcw2 * hval[3];
        pr  += __shfl_xor_sync(0xffffffffu, pr, 1);
        pr  += __shfl_xor_sync(0xffffffffu, pr, 2);
        pr8 += __shfl_xor_sync(0xffffffffu, pr8, 1);
        pr8 += __shfl_xor_sync(0xffffffffu, pr8, 2);
        if (q == 0) {
            psum[t & 1][r][wid] = pr;
            psum[t & 1][r + 8][wid] = pr8;
        }
        xv0 = pxv0;
        xv1 = pxv1;
        __syncthreads();
    }

    // final flush
    if (wid == 0 && lane < 16) {
        const float* ps = &psum[(T_LEN - 1) & 1][lane][0];
        float s = 0.f;
        #pragma unroll
        for (int j = 0; j < 8; ++j) s += ps[j];
        atomicAdd(out + (size_t)(b0 + lane) * T_LEN + (T_LEN - 1), s);
    }
}

extern "C" void kernel_launch(void* const* d_in, const int* in_sizes, int n_in,
                              void* d_out, int out_size) {
    const float* x     = (const float*)d_in[0];
    const float* Wih_f = (const float*)d_in[1];
    const float* Whh_f = (const float*)d_in[2];
    const float* bih_f = (const float*)d_in[3];
    const float* bhh_f = (const float*)d_in[4];
    const float* Wih_b = (const float*)d_in[5];
    const float* Whh_b = (const float*)d_in[6];
    const float* bih_b = (const float*)d_in[7];
    const float* bhh_b = (const float*)d_in[8];
    const float* fc_w  = (const float*)d_in[9];
    const float* fc_b  = (const float*)d_in[10];
    float* out = (float*)d_out;

    out_init<<<(out_size + 255) / 256, 256>>>(out, fc_b, out_size);

    const int B = in_sizes[0] / T_LEN;   // 1024
    const int grid = (B / 16) * 2;       // 128 CTAs: (batch-group, direction)
    bilstm_mma<<<grid, NTH>>>(x, Wih_f, Whh_f, bih_f, bhh_f,
                              Wih_b, Whh_b, bih_b, bhh_b, fc_w, out);
    (void)n_in;
}

// round 15
// speedup vs baseline: 1.1825x; 1.1104x over previous
#include <cuda_runtime.h>
#include <cuda_fp16.h>
#include <cstdint>

#define T_LEN 1024
#define NTH   256
#define HSTR  72         // halves per row (144 B = 9*16B): 16B-aligned, conflict-free

static __device__ __forceinline__ float tanhapx(float x) {
    float y;
    asm("tanh.approx.f32 %0, %1;" : "=f"(y) : "f"(x));
    return y;
}
static __device__ __forceinline__ float fsig(float x) {
    return fmaf(0.5f, tanhapx(0.5f * x), 0.5f);
}
static __device__ __forceinline__ uint32_t pack2w(float a, float b) {
    __half2 t = __halves2half2(__float2half_rn(a), __float2half_rn(b));
    return *(uint32_t*)&t;
}
// 64-col permutation: h col c -> fragment-vectorized position (validated R10/R11)
static __device__ __forceinline__ int perm64(int c) {
    return (((c & 7) >> 1) << 4) + ((c >> 4) << 2) + (((c >> 3) & 1) << 1) + (c & 1);
}
static __device__ __forceinline__ void mma16816(float* d, const uint32_t* a, const uint32_t* b) {
    asm volatile(
        "mma.sync.aligned.m16n8k16.row.col.f32.f16.f16.f32 "
        "{%0,%1,%2,%3}, {%4,%5,%6,%7}, {%8,%9}, {%0,%1,%2,%3};"
        : "+f"(d[0]), "+f"(d[1]), "+f"(d[2]), "+f"(d[3])
        : "r"(a[0]), "r"(a[1]), "r"(a[2]), "r"(a[3]), "r"(b[0]), "r"(b[1]));
}

__global__ void out_init(float* out, const float* fc_b, int n) {
    int i = blockIdx.x * blockDim.x + threadIdx.x;
    if (i < n) out[i] = fc_b[0];
}

__global__ __launch_bounds__(NTH, 1)
void bilstm_mma(const float* __restrict__ x,
                const float* __restrict__ Wih_f, const float* __restrict__ Whh_f,
                const float* __restrict__ bih_f, const float* __restrict__ bhh_f,
                const float* __restrict__ Wih_b, const float* __restrict__ Whh_b,
                const float* __restrict__ bih_b, const float* __restrict__ bhh_b,
                const float* __restrict__ fc_w, float* __restrict__ out)
{
    __shared__ __align__(16) __half hs[2][16][HSTR];   // h (fp16) in frag-permuted order
    __shared__ float psum[2][16][8];

    const int tid = threadIdx.x, wid = tid >> 5, lane = tid & 31;
    const int q = lane & 3, r = lane >> 2;
    const int dir = blockIdx.x & 1;
    const int b0 = (blockIdx.x >> 1) * 16;

    const float* Whh = dir ? Whh_b : Whh_f;
    const float* Wih = dir ? Wih_b : Wih_f;
    const float* bih = dir ? bih_b : bih_f;
    const float* bhh = dir ? bhh_b : bhh_f;

    for (int i = tid; i < 2 * 16 * HSTR; i += NTH) (&hs[0][0][0])[i] = __float2half(0.f);

    // ---- B fragments (Whh^T), pure fp16 W: bf[ks 0..3][nt 0..3][2] ----
    uint32_t bf[4][4][2];
    {
        const int qp = r >> 1, odd = r & 1;
        #pragma unroll
        for (int nt = 0; nt < 4; ++nt) {
            const int unit = 8 * wid + (nt >= 2 ? 4 : 0) + qp;
            const int row = ((nt & 1) ? (odd ? 192 : 64) : (odd ? 128 : 0)) + unit;
            const float* wr = Whh + row * 64;
            #pragma unroll
            for (int ks = 0; ks < 4; ++ks) {
                const int wcol = ks * 16 + q * 2;
                bf[ks][nt][0] = pack2w(__ldg(wr + wcol),     __ldg(wr + wcol + 1));
                bf[ks][nt][1] = pack2w(__ldg(wr + wcol + 8), __ldg(wr + wcol + 9));
            }
        }
    }

    // gate-owner: units u1 = 8*wid+q, u2 = u1+4; streams r, r+8
    const int u1 = 8 * wid + q, u2 = u1 + 4;
    const float wi_i1 = Wih[u1], wi_f1 = Wih[64 + u1], wi_g1 = Wih[128 + u1], wi_o1 = Wih[192 + u1];
    const float wi_i2 = Wih[u2], wi_f2 = Wih[64 + u2], wi_g2 = Wih[128 + u2], wi_o2 = Wih[192 + u2];
    const float bi1 = bih[u1] + bhh[u1],             bf1 = bih[64 + u1] + bhh[64 + u1];
    const float bg1 = bih[128 + u1] + bhh[128 + u1], bo1 = bih[192 + u1] + bhh[192 + u1];
    const float bi2 = bih[u2] + bhh[u2],             bf2 = bih[64 + u2] + bhh[64 + u2];
    const float bg2 = bih[128 + u2] + bhh[128 + u2], bo2 = bih[192 + u2] + bhh[192 + u2];
    const float fcw1 = fc_w[dir * 64 + u1], fcw2 = fc_w[dir * 64 + u2];
    const int pc1 = perm64(u1), pc2 = perm64(u2);

    float cc[4] = {0.f, 0.f, 0.f, 0.f};
    __syncthreads();

    // x prefetch for t = 0
    const float* xr0 = x + (size_t)(b0 + r) * T_LEN;
    const float* xr1 = x + (size_t)(b0 + r + 8) * T_LEN;
    float xv0 = __ldg(xr0 + (dir ? T_LEN - 1 : 0));
    float xv1 = __ldg(xr1 + (dir ? T_LEN - 1 : 0));

    for (int t = 0; t < T_LEN; ++t) {
        // prefetch x(t+1) — hides L2 latency under this step's compute
        float pxv0 = 0.f, pxv1 = 0.f;
        if (t + 1 < T_LEN) {
            const int nxt = dir ? (T_LEN - 2 - t) : (t + 1);
            pxv0 = __ldg(xr0 + nxt);
            pxv1 = __ldg(xr1 + nxt);
        }

        // flush previous step's fc partials (off critical path)
        if (t > 0 && wid == 0 && lane < 16) {
            const float* ps = &psum[(t - 1) & 1][lane][0];
            float s = 0.f;
            #pragma unroll
            for (int j = 0; j < 8; ++j) s += ps[j];
            atomicAdd(out + (size_t)(b0 + lane) * T_LEN + (t - 1), s);
        }

        // ---- A fragments: 4x LDS.128 from permuted buffer ----
        const __half* hb = &hs[(t & 1) ^ 1][0][0];
        uint32_t af[4][4];
        {
            const uint4* p0 = (const uint4*)(hb + r * HSTR + q * 16);
            const uint4* p1 = (const uint4*)(hb + (r + 8) * HSTR + q * 16);
            #pragma unroll
            for (int m = 0; m < 2; ++m) {
                const uint4 v = p0[m];
                af[2*m][0] = v.x; af[2*m][2] = v.y; af[2*m+1][0] = v.z; af[2*m+1][2] = v.w;
                const uint4 u = p1[m];
                af[2*m][1] = u.x; af[2*m][3] = u.y; af[2*m+1][1] = u.z; af[2*m+1][3] = u.w;
            }
        }

        // ---- all 16 HMMA first: 4 independent accumulation chains pipeline deeply ----
        float d[4][4] = {{0.f,0.f,0.f,0.f},{0.f,0.f,0.f,0.f},{0.f,0.f,0.f,0.f},{0.f,0.f,0.f,0.f}};
        #pragma unroll
        for (int ks = 0; ks < 4; ++ks) {
            mma16816(d[0], af[ks], bf[ks][0]);
            mma16816(d[1], af[ks], bf[ks][1]);
            mma16816(d[2], af[ks], bf[ks][2]);
            mma16816(d[3], af[ks], bf[ks][3]);
        }

        // ---- gates: 4 independent (unit, stream) chains, interleaved by compiler ----
        __half* hw = &hs[t & 1][0][0];
        float hval[4];
        #pragma unroll
        for (int cidx = 0; cidx < 4; ++cidx) {
            const bool isU2 = cidx >= 2;
            const int ti = isU2 ? 2 : 0;
            const int co = (cidx & 1) * 2;
            const float xv = (cidx & 1) ? xv1 : xv0;
            const float zi = d[ti][co]     + fmaf(xv, isU2 ? wi_i2 : wi_i1, isU2 ? bi2 : bi1);
            const float zg = d[ti][co + 1] + fmaf(xv, isU2 ? wi_g2 : wi_g1, isU2 ? bg2 : bg1);
            const float zf = d[ti + 1][co]     + fmaf(xv, isU2 ? wi_f2 : wi_f1, isU2 ? bf2 : bf1);
            const float zo = d[ti + 1][co + 1] + fmaf(xv, isU2 ? wi_o2 : wi_o1, isU2 ? bo2 : bo1);
            cc[cidx] = fmaf(fsig(zf), cc[cidx], fsig(zi) * tanhapx(zg));
            hval[cidx] = fsig(zo) * tanhapx(cc[cidx]);
            hw[((cidx & 1) ? (r + 8) : r) * HSTR + (isU2 ? pc2 : pc1)] = __float2half_rn(hval[cidx]);
        }

        // ---- fc partials ----
        float pr  = fcw1 * hval[0] + fcw2 * hval[2];
        float pr8 = fcw1 * hval[1] + fcw2 * hval[3];
        pr  += __shfl_xor_sync(0xffffffffu, pr, 1);
        pr  += __shfl_xor_sync(0xffffffffu, pr, 2);
        pr8 += __shfl_xor_sync(0xffffffffu, pr8, 1);
        pr8 += __shfl_xor_sync(0xffffffffu, pr8, 2);
        if (q == 0) {
            psum[t & 1][r][wid] = pr;
            psum[t & 1][r + 8][wid] = pr8;
        }
        xv0 = pxv0;
        xv1 = pxv1;
        __syncthreads();
    }

    // final flush
    if (wid == 0 && lane < 16) {
        const float* ps = &psum[(T_LEN - 1) & 1][lane][0];
        float s = 0.f;
        #pragma unroll
        for (int j = 0; j < 8; ++j) s += ps[j];
        atomicAdd(out + (size_t)(b0 + lane) * T_LEN + (T_LEN - 1), s);
    }
}

extern "C" void kernel_launch(void* const* d_in, const int* in_sizes, int n_in,
                              void* d_out, int out_size) {
    const float* x     = (const float*)d_in[0];
    const float* Wih_f = (const float*)d_in[1];
    const float* Whh_f = (const float*)d_in[2];
    const float* bih_f = (const float*)d_in[3];
    const float* bhh_f = (const float*)d_in[4];
    const float* Wih_b = (const float*)d_in[5];
    const float* Whh_b = (const float*)d_in[6];
    const float* bih_b = (const float*)d_in[7];
    const float* bhh_b = (const float*)d_in[8];
    const float* fc_w  = (const float*)d_in[9];
    const float* fc_b  = (const float*)d_in[10];
    float* out = (float*)d_out;

    out_init<<<(out_size + 255) / 256, 256>>>(out, fc_b, out_size);

    const int B = in_sizes[0] / T_LEN;   // 1024
    const int grid = (B / 16) * 2;       // 128 CTAs: (batch-group, direction)
    bilstm_mma<<<grid, NTH>>>(x, Wih_f, Whh_f, bih_f, bhh_f,
                              Wih_b, Whh_b, bih_b, bhh_b, fc_w, out);
    (void)n_in;
}